// round 15
// baseline (speedup 1.0000x reference)
#include <cuda_runtime.h>
#include <cuda_fp16.h>
#include <cstdint>

#define OC 32
#define ICAP 1024
#define BSZ 64
#define DD 64
#define EE 64

// ---------------- scratch (static device globals; no allocation) ----------------
__device__ __half u_buf[(size_t)ICAP * OC * BSZ * EE];          // 268 MB
__device__ __half xh_buf[(size_t)ICAP * BSZ * DD];              // 8 MB
__device__ __half xl_buf[(size_t)ICAP * BSZ * DD];              // 8 MB
__device__ float  beta_buf[(size_t)ICAP * BSZ * OC];            // 8 MB
__device__ float  S0_buf[OC * BSZ * EE];
__device__ float  S1_buf[OC * BSZ * EE];
__device__ float  S2_buf[OC * BSZ * EE];
__device__ float  v0_buf[OC * BSZ * EE];
__device__ float  v1_buf[OC * BSZ * EE];
__device__ int    cnt_buf[3];                                   // zero-init; self-resetting

#define FMA2(d_, a_, b_, c_) \
    asm("fma.rn.f32x2 %0, %1, %2, %3;" : "=l"(d_) : "l"(a_), "l"(b_), "l"(c_))
union F2U { unsigned long long u; float2 f; };

__device__ __forceinline__ uint32_t smem_u32(const void* p) {
    uint32_t a;
    asm("{ .reg .u64 t; cvta.to.shared.u64 t, %1; cvt.u32.u64 %0, t; }" : "=r"(a) : "l"(p));
    return a;
}

#define LDM_X4(r0, r1, r2, r3, addr) \
    asm volatile("ldmatrix.sync.aligned.m8n8.x4.shared.b16 {%0,%1,%2,%3}, [%4];" \
        : "=r"(r0), "=r"(r1), "=r"(r2), "=r"(r3) : "r"(addr))
#define LDM_X2_T(r0, r1, addr) \
    asm volatile("ldmatrix.sync.aligned.m8n8.x2.trans.shared.b16 {%0,%1}, [%2];" \
        : "=r"(r0), "=r"(r1) : "r"(addr))
#define MMA16816(c, a0, a1, a2, a3, b0, b1) \
    asm volatile("mma.sync.aligned.m16n8k16.row.col.f32.f16.f16.f32 " \
        "{%0,%1,%2,%3}, {%4,%5,%6,%7}, {%8,%9}, {%0,%1,%2,%3};" \
        : "+f"((c)[0]), "+f"((c)[1]), "+f"((c)[2]), "+f"((c)[3]) \
        : "r"(a0), "r"(a1), "r"(a2), "r"(a3), "r"(b0), "r"(b1))
#define CP_ASYNC16(dst, src) \
    asm volatile("cp.async.cg.shared.global [%0], [%1], 16;" :: "r"(dst), "l"(src) : "memory")
#define CP_COMMIT() asm volatile("cp.async.commit_group;" ::: "memory")
#define CP_WAIT1()  asm volatile("cp.async.wait_group 1;" ::: "memory")

// ---------------- fused squash (run by the LAST CTA of a producer kernel) -------
__device__ __forceinline__ void squash_block(const float* __restrict__ Sin,
                                             float* __restrict__ vout,
                                             float factor, int tid, int nthreads) {
    int warp = tid >> 5, lane = tid & 31;
    int nw = nthreads >> 5;
    for (int row = warp; row < OC * BSZ; row += nw) {
        float a = Sin[row * 64 + lane] * factor;
        float c = Sin[row * 64 + 32 + lane] * factor;
        float sq = a * a + c * c;
        #pragma unroll
        for (int s = 16; s; s >>= 1) sq += __shfl_xor_sync(0xffffffffu, sq, s);
        float scale = sqrtf(sq) / (1.0f + sq);
        vout[row * 64 + lane]      = a * scale;
        vout[row * 64 + 32 + lane] = c * scale;
    }
}

// ---------------- kernel 0: split x into fp16 hi/lo + zero S buffers ------------
__global__ void __launch_bounds__(256) xsplit_kernel(const float* __restrict__ x) {
    size_t idx = (size_t)blockIdx.x * 256 + threadIdx.x;   // float4 index
    if (idx < (size_t)OC * BSZ * EE) {
        S0_buf[idx] = 0.f; S1_buf[idx] = 0.f; S2_buf[idx] = 0.f;
    }
    float4 v = ((const float4*)x)[idx];
    __half hx = __float2half_rn(v.x), hy = __float2half_rn(v.y);
    __half hz = __float2half_rn(v.z), hw = __float2half_rn(v.w);
    __half lx = __float2half_rn(v.x - __half2float(hx));
    __half ly = __float2half_rn(v.y - __half2float(hy));
    __half lz = __float2half_rn(v.z - __half2float(hz));
    __half lw = __float2half_rn(v.w - __half2float(hw));
    __half2 h01 = __halves2half2(hx, hy), h23 = __halves2half2(hz, hw);
    __half2 l01 = __halves2half2(lx, ly), l23 = __halves2half2(lz, lw);
    uint2 ph, pl;
    ph.x = *(unsigned*)&h01; ph.y = *(unsigned*)&h23;
    pl.x = *(unsigned*)&l01; pl.y = *(unsigned*)&l23;
    ((uint2*)xh_buf)[idx] = ph;
    ((uint2*)xl_buf)[idx] = pl;
}

// ---------------- kernel 1: HMMA GEMM — cp.async x staging + fused squash0 ------
#define G_IPB 32
#define XP 72
#define TILE_B (64 * XP * 2)
#define OFF_XH0 0
#define OFF_XH1 (1 * TILE_B)
#define OFF_XL0 (2 * TILE_B)
#define OFF_XL1 (3 * TILE_B)
#define OFF_WS  (4 * TILE_B)
#define OFF_CS  (5 * TILE_B)
#define DSM_TOTAL (6 * TILE_B)             // 55296 B

__global__ void __launch_bounds__(256, 2) gemm_kernel(const float* __restrict__ w) {
    extern __shared__ __align__(16) char dsm[];
    __shared__ int is_last;
    const uint32_t smb = smem_u32(dsm);

    const int tid  = threadIdx.x;
    const int wid  = tid >> 5;
    const int lane = tid & 31;
    const int o    = blockIdx.x;
    const int ic   = blockIdx.y;

    const int mtile = wid & 3;
    const int ehalf = wid >> 2;
    const int bbase = mtile * 16;
    const int ebase = ehalf * 32;

    const int am = (((lane >> 3) & 1) * 8) + (lane & 7);
    const int ak = (lane >> 4) * 8;
    const uint32_t aoff = (uint32_t)(((bbase + am) * XP + ak) * 2);
    const uint32_t boff = (uint32_t)(((lane & 15) * XP + ebase) * 2) + OFF_WS;

    const int ecol = 2 * (lane & 3);
    const int brow = lane >> 2;

    const int xb0 = tid >> 3,         xd0 = (tid & 7) * 8;
    const int xb1 = (tid + 256) >> 3, xd1 = (tid & 7) * 8;
    const uint32_t xs_off0 = (uint32_t)((xb0 * XP + xd0) * 2);
    const uint32_t xs_off1 = (uint32_t)((xb1 * XP + xd1) * 2);
    const size_t   xg_off0 = (size_t)xb0 * 64 + xd0;
    const size_t   xg_off1 = (size_t)xb1 * 64 + xd1;

    __half* ws = (__half*)(dsm + OFF_WS);
    __half* cs = (__half*)(dsm + OFF_CS);

    float s0[16];
    #pragma unroll
    for (int j = 0; j < 16; j++) s0[j] = 0.f;

    float4 wq[4];
    {
        const int i = ic * G_IPB;
        const __half* xh = xh_buf + (size_t)i * (BSZ * DD);
        const __half* xl = xl_buf + (size_t)i * (BSZ * DD);
        CP_ASYNC16(smb + OFF_XH0 + xs_off0, xh + xg_off0);
        CP_ASYNC16(smb + OFF_XH0 + xs_off1, xh + xg_off1);
        CP_ASYNC16(smb + OFF_XL0 + xs_off0, xl + xg_off0);
        CP_ASYNC16(smb + OFF_XL0 + xs_off1, xl + xg_off1);
        CP_COMMIT();
        const float4* wg = (const float4*)(w + (((size_t)o * ICAP + i) << 12));
        #pragma unroll
        for (int q = 0; q < 4; q++) wq[q] = wg[q * 256 + tid];
    }

    for (int ii = 0; ii < G_IPB; ii++) {
        const int i = ic * G_IPB + ii;
        const int p = ii & 1;
        const uint32_t xh_p  = (p ? OFF_XH1 : OFF_XH0);
        const uint32_t xl_p  = (p ? OFF_XL1 : OFF_XL0);
        const uint32_t xh_q  = (p ? OFF_XH0 : OFF_XH1);
        const uint32_t xl_q  = (p ? OFF_XL0 : OFF_XL1);

        #pragma unroll
        for (int q = 0; q < 4; q++) {
            int f4 = q * 256 + tid;
            int d  = f4 >> 4;
            int e4 = (f4 & 15) << 2;
            __half2 h01 = __floats2half2_rn(wq[q].x, wq[q].y);
            __half2 h23 = __floats2half2_rn(wq[q].z, wq[q].w);
            uint2 pk;
            pk.x = *(unsigned*)&h01; pk.y = *(unsigned*)&h23;
            *(uint2*)&ws[d * XP + e4] = pk;
        }

        if (ii + 1 < G_IPB) {
            const int in = i + 1;
            const __half* xh = xh_buf + (size_t)in * (BSZ * DD);
            const __half* xl = xl_buf + (size_t)in * (BSZ * DD);
            CP_ASYNC16(smb + xh_q + xs_off0, xh + xg_off0);
            CP_ASYNC16(smb + xh_q + xs_off1, xh + xg_off1);
            CP_ASYNC16(smb + xl_q + xs_off0, xl + xg_off0);
            CP_ASYNC16(smb + xl_q + xs_off1, xl + xg_off1);
        }
        CP_COMMIT();
        if (ii + 1 < G_IPB) {
            const float4* wg = (const float4*)(w + (((size_t)o * ICAP + i + 1) << 12));
            #pragma unroll
            for (int q = 0; q < 4; q++) wq[q] = wg[q * 256 + tid];
        }

        CP_WAIT1();
        __syncthreads();

        const uint32_t a_h = smb + xh_p + aoff;
        const uint32_t a_l = smb + xl_p + aoff;
        const uint32_t b_0 = smb + boff;

        float c[16];
        #pragma unroll
        for (int j = 0; j < 16; j++) c[j] = 0.f;

        #pragma unroll
        for (int kt = 0; kt < 4; kt++) {
            uint32_t ah0, ah1, ah2, ah3, al0, al1, al2, al3;
            LDM_X4(ah0, ah1, ah2, ah3, a_h + kt * 32);
            LDM_X4(al0, al1, al2, al3, a_l + kt * 32);
            #pragma unroll
            for (int nt = 0; nt < 4; nt++) {
                uint32_t b0, b1;
                LDM_X2_T(b0, b1, b_0 + kt * (16 * XP * 2) + nt * 16);
                MMA16816(&c[nt * 4], ah0, ah1, ah2, ah3, b0, b1);
                MMA16816(&c[nt * 4], al0, al1, al2, al3, b0, b1);
            }
        }

        #pragma unroll
        for (int nt = 0; nt < 4; nt++) {
            #pragma unroll
            for (int j = 0; j < 4; j++) s0[nt * 4 + j] += c[nt * 4 + j];
            int e0 = ebase + nt * 8 + ecol;
            __half2 p0 = __floats2half2_rn(c[nt * 4 + 0], c[nt * 4 + 1]);
            __half2 p1 = __floats2half2_rn(c[nt * 4 + 2], c[nt * 4 + 3]);
            *(__half2*)&cs[(bbase + brow) * XP + e0]     = p0;
            *(__half2*)&cs[(bbase + brow + 8) * XP + e0] = p1;
        }
        __syncthreads();

        {
            uint4* ubase = (uint4*)(u_buf + ((size_t)i * OC + o) * (BSZ * EE));
            int t0 = tid, t1 = tid + 256;
            ubase[t0] = *(uint4*)&cs[(t0 >> 3) * XP + (t0 & 7) * 8];
            ubase[t1] = *(uint4*)&cs[(t1 >> 3) * XP + (t1 & 7) * 8];
        }
    }

    #pragma unroll
    for (int nt = 0; nt < 4; nt++) {
        int e0 = ebase + nt * 8 + ecol;
        int b0 = bbase + brow;
        atomicAdd(&S0_buf[(o * BSZ + b0) * EE + e0],     s0[nt * 4 + 0]);
        atomicAdd(&S0_buf[(o * BSZ + b0) * EE + e0 + 1], s0[nt * 4 + 1]);
        atomicAdd(&S0_buf[(o * BSZ + b0 + 8) * EE + e0],     s0[nt * 4 + 2]);
        atomicAdd(&S0_buf[(o * BSZ + b0 + 8) * EE + e0 + 1], s0[nt * 4 + 3]);
    }

    // ---- last CTA computes v0 = squash(S0/32)
    __threadfence();
    if (tid == 0)
        is_last = (atomicAdd(&cnt_buf[0], 1) == (int)(gridDim.x * gridDim.y) - 1);
    __syncthreads();
    if (is_last) {
        squash_block(S0_buf, v0_buf, 1.0f / 32.0f, tid, 256);
        if (tid == 0) cnt_buf[0] = 0;
    }
}

// ---------------- routing scan (R11 version) + fused squash ----------------
#define RIPB 32
__global__ void __launch_bounds__(128, 2) route_iter_kernel(int phase, float* __restrict__ outp) {
    const float* vprev = (phase == 1) ? v0_buf : v1_buf;
    float* Sout        = (phase == 1) ? S1_buf : S2_buf;
    float* vnext       = (phase == 1) ? v1_buf : outp;

    __shared__ float esum[2][2][2][2];
    __shared__ float Sred[4][16][66];
    __shared__ int   is_last;

    const int b    = blockIdx.x;
    const int i0   = blockIdx.y * RIPB;
    const int tid  = threadIdx.x;
    const int warp = tid >> 5;
    const int L    = tid & 31;
    const int w    = warp & 1;
    const int ig   = warp >> 1;
    const int g    = L >> 3;
    const int p    = L & 7;

    unsigned long long vs[4][4];
    #pragma unroll
    for (int k = 0; k < 4; k++) {
        int o = w * 16 + k * 4 + g;
        const float4* vg = (const float4*)(vprev + (o * BSZ + b) * EE + p * 8);
        float4 v0 = vg[0], v1 = vg[1];
        F2U t0, t1, t2, t3;
        t0.f = make_float2(v0.x, v0.y); t1.f = make_float2(v0.z, v0.w);
        t2.f = make_float2(v1.x, v1.y); t3.f = make_float2(v1.z, v1.w);
        vs[k][0] = t0.u; vs[k][1] = t1.u; vs[k][2] = t2.u; vs[k][3] = t3.u;
    }

    unsigned long long S[4][4];
    #pragma unroll
    for (int k = 0; k < 4; k++)
        #pragma unroll
        for (int j = 0; j < 4; j++) S[k][j] = 0ull;

    const uint4* ub4 = (const uint4*)u_buf;
    const uint4* bb4 = (const uint4*)beta_buf;
    const int lconst = g * 512 + p;

    uint4 qA[2][4], qB[2][4];
    float4 bpA[2], bpB[2];

    {
        const int iA = i0 + ig, iB = iA + 2;
        const size_t baseA = (((size_t)iA * OC + w * 16) * BSZ + b) * 8;
        const size_t baseB = (((size_t)iB * OC + w * 16) * BSZ + b) * 8;
        #pragma unroll
        for (int k = 0; k < 4; k++) {
            qA[0][k] = __ldg(ub4 + baseA + k * 2048 + lconst);
            qB[0][k] = __ldg(ub4 + baseB + k * 2048 + lconst);
        }
        if (phase == 2) {
            bpA[0] = *(const float4*)(bb4 + ((((size_t)iA * BSZ + b) * 2 + w) * 4 + g));
            bpB[0] = *(const float4*)(bb4 + ((((size_t)iB * BSZ + b) * 2 + w) * 4 + g));
        }
    }

    #pragma unroll
    for (int tb = 0; tb < 8; tb++) {
        const int cur = tb & 1, nxt = cur ^ 1;
        const int iA = i0 + tb * 4 + ig;
        const int iB = iA + 2;

        if (tb < 7) {
            const int jA = iA + 4, jB = iB + 4;
            const size_t baseA = (((size_t)jA * OC + w * 16) * BSZ + b) * 8;
            const size_t baseB = (((size_t)jB * OC + w * 16) * BSZ + b) * 8;
            #pragma unroll
            for (int k = 0; k < 4; k++) {
                qA[nxt][k] = __ldg(ub4 + baseA + k * 2048 + lconst);
                qB[nxt][k] = __ldg(ub4 + baseB + k * 2048 + lconst);
            }
            if (phase == 2) {
                bpA[nxt] = *(const float4*)(bb4 + ((((size_t)jA * BSZ + b) * 2 + w) * 4 + g));
                bpB[nxt] = *(const float4*)(bb4 + ((((size_t)jB * BSZ + b) * 2 + w) * 4 + g));
            }
        }

        float betA[4], betB[4];
        #pragma unroll
        for (int k = 0; k < 4; k++) {
            unsigned long long dA = 0ull, dB = 0ull;
            const __half2* hA = (const __half2*)&qA[cur][k];
            const __half2* hB = (const __half2*)&qB[cur][k];
            #pragma unroll
            for (int j = 0; j < 4; j++) {
                F2U a; a.f = __half22float2(hA[j]);
                FMA2(dA, a.u, vs[k][j], dA);
                F2U c; c.f = __half22float2(hB[j]);
                FMA2(dB, c.u, vs[k][j], dB);
            }
            F2U rA; rA.u = dA; float fA = rA.f.x + rA.f.y;
            F2U rB; rB.u = dB; float fB = rB.f.x + rB.f.y;
            #pragma unroll
            for (int s = 1; s < 8; s <<= 1) {
                fA += __shfl_xor_sync(0xffffffffu, fA, s);
                fB += __shfl_xor_sync(0xffffffffu, fB, s);
            }
            betA[k] = fA; betB[k] = fB;
        }

        if (phase == 2) {
            betA[0] += bpA[cur].x; betA[1] += bpA[cur].y;
            betA[2] += bpA[cur].z; betA[3] += bpA[cur].w;
            betB[0] += bpB[cur].x; betB[1] += bpB[cur].y;
            betB[2] += bpB[cur].z; betB[3] += bpB[cur].w;
        } else if (p == 0) {
            *(uint4*)(bb4 + ((((size_t)iA * BSZ + b) * 2 + w) * 4 + g)) = *(uint4*)betA;
            *(uint4*)(bb4 + ((((size_t)iB * BSZ + b) * 2 + w) * 4 + g)) = *(uint4*)betB;
        }

        float eA[4], eB[4], sA = 0.f, sB = 0.f;
        #pragma unroll
        for (int k = 0; k < 4; k++) {
            eA[k] = __expf(betA[k]); sA += eA[k];
            eB[k] = __expf(betB[k]); sB += eB[k];
        }
        sA += __shfl_xor_sync(0xffffffffu, sA, 8);
        sA += __shfl_xor_sync(0xffffffffu, sA, 16);
        sB += __shfl_xor_sync(0xffffffffu, sB, 8);
        sB += __shfl_xor_sync(0xffffffffu, sB, 16);

        if (L == 0) { esum[cur][ig][0][w] = sA; esum[cur][ig][1][w] = sB; }
        asm volatile("bar.sync %0, %1;" :: "r"(1 + ig), "r"(64) : "memory");
        float rA = __fdividef(1.f, sA + esum[cur][ig][0][w ^ 1]);
        float rB = __fdividef(1.f, sB + esum[cur][ig][1][w ^ 1]);

        #pragma unroll
        for (int k = 0; k < 4; k++) {
            F2U cdA; float cA = eA[k] * rA; cdA.f = make_float2(cA, cA);
            F2U cdB; float cB = eB[k] * rB; cdB.f = make_float2(cB, cB);
            const __half2* hA = (const __half2*)&qA[cur][k];
            const __half2* hB = (const __half2*)&qB[cur][k];
            #pragma unroll
            for (int j = 0; j < 4; j++) {
                F2U a; a.f = __half22float2(hA[j]);
                FMA2(S[k][j], cdA.u, a.u, S[k][j]);
                F2U c; c.f = __half22float2(hB[j]);
                FMA2(S[k][j], cdB.u, c.u, S[k][j]);
            }
        }
    }

    #pragma unroll
    for (int k = 0; k < 4; k++)
        #pragma unroll
        for (int j = 0; j < 4; j++) {
            F2U s; s.u = S[k][j];
            Sred[warp][k * 4 + g][p * 8 + 2 * j]     = s.f.x;
            Sred[warp][k * 4 + g][p * 8 + 2 * j + 1] = s.f.y;
        }
    __syncthreads();

    for (int t = tid; t < 2048; t += 128) {
        int half = t >> 10;
        int row  = (t >> 6) & 15;
        int e    = t & 63;
        float v = Sred[half][row][e] + Sred[2 + half][row][e];
        int o = half * 16 + row;
        atomicAdd(&Sout[(o * BSZ + b) * EE + e], v);
    }

    // ---- last CTA computes the squash (replaces separate launch)
    __threadfence();
    if (tid == 0)
        is_last = (atomicAdd(&cnt_buf[phase], 1) == (int)(gridDim.x * gridDim.y) - 1);
    __syncthreads();
    if (is_last) {
        squash_block(Sout, vnext, 1.0f, tid, 128);
        if (tid == 0) cnt_buf[phase] = 0;
    }
}

// ---------------- launch ----------------
extern "C" void kernel_launch(void* const* d_in, const int* in_sizes, int n_in,
                              void* d_out, int out_size) {
    const float* x = (const float*)d_in[0];       // [1024, 64, 64]
    const float* w = (const float*)d_in[1];       // [32, 1024, 64, 64]
    if (n_in >= 2 && in_sizes[0] > in_sizes[1]) { const float* t = x; x = w; w = t; }
    float* out = (float*)d_out;                   // [32, 64, 64]

    cudaFuncSetAttribute(gemm_kernel, cudaFuncAttributeMaxDynamicSharedMemorySize,
                         DSM_TOTAL);

    xsplit_kernel<<<4096, 256>>>(x);              // also zeroes S0/S1/S2

    dim3 gG(OC, ICAP / G_IPB);                    // (32 o, 32 i-chunks)
    gemm_kernel<<<gG, 256, DSM_TOTAL>>>(w);       // + fused squash0 -> v0

    dim3 gR(BSZ, ICAP / RIPB);                    // (64, 32)
    route_iter_kernel<<<gR, 128>>>(1, nullptr);   // + fused squash1 -> v1
    route_iter_kernel<<<gR, 128>>>(2, out);       // + fused squash2 -> out
}

// round 16
// speedup vs baseline: 2.8162x; 2.8162x over previous
#include <cuda_runtime.h>
#include <cuda_fp16.h>
#include <cstdint>

#define OC 32
#define ICAP 1024
#define BSZ 64
#define DD 64
#define EE 64

// ---------------- scratch (static device globals; no allocation) ----------------
// u fp16, layout [i][o][b][e] — contiguous 8KB tile per (i,o); coalesced loads.
__device__ __half u_buf[(size_t)ICAP * OC * BSZ * EE];          // 268 MB
__device__ __half xh_buf[(size_t)ICAP * BSZ * DD];              // 8 MB
__device__ __half xl_buf[(size_t)ICAP * BSZ * DD];              // 8 MB
// beta permuted layout: [i][b][w][g][k] floats
__device__ float  beta_buf[(size_t)ICAP * BSZ * OC];            // 8 MB
__device__ float  S0_buf[OC * BSZ * EE];
__device__ float  S1_buf[OC * BSZ * EE];
__device__ float  S2_buf[OC * BSZ * EE];
__device__ float  v0_buf[OC * BSZ * EE];
__device__ float  v1_buf[OC * BSZ * EE];

#define FMA2(d_, a_, b_, c_) \
    asm("fma.rn.f32x2 %0, %1, %2, %3;" : "=l"(d_) : "l"(a_), "l"(b_), "l"(c_))
union F2U { unsigned long long u; float2 f; };

__device__ __forceinline__ uint32_t smem_u32(const void* p) {
    uint32_t a;
    asm("{ .reg .u64 t; cvta.to.shared.u64 t, %1; cvt.u32.u64 %0, t; }" : "=r"(a) : "l"(p));
    return a;
}

#define LDM_X4(r0, r1, r2, r3, addr) \
    asm volatile("ldmatrix.sync.aligned.m8n8.x4.shared.b16 {%0,%1,%2,%3}, [%4];" \
        : "=r"(r0), "=r"(r1), "=r"(r2), "=r"(r3) : "r"(addr))
#define LDM_X2_T(r0, r1, addr) \
    asm volatile("ldmatrix.sync.aligned.m8n8.x2.trans.shared.b16 {%0,%1}, [%2];" \
        : "=r"(r0), "=r"(r1) : "r"(addr))
#define MMA16816(c, a0, a1, a2, a3, b0, b1) \
    asm volatile("mma.sync.aligned.m16n8k16.row.col.f32.f16.f16.f32 " \
        "{%0,%1,%2,%3}, {%4,%5,%6,%7}, {%8,%9}, {%0,%1,%2,%3};" \
        : "+f"((c)[0]), "+f"((c)[1]), "+f"((c)[2]), "+f"((c)[3]) \
        : "r"(a0), "r"(a1), "r"(a2), "r"(a3), "r"(b0), "r"(b1))
#define CP_ASYNC16(dst, src) \
    asm volatile("cp.async.cg.shared.global [%0], [%1], 16;" :: "r"(dst), "l"(src) : "memory")
#define CP_COMMIT() asm volatile("cp.async.commit_group;" ::: "memory")
#define CP_WAIT1()  asm volatile("cp.async.wait_group 1;" ::: "memory")

// ---------------- kernel 0: split x into fp16 hi/lo + zero S buffers ------------
__global__ void __launch_bounds__(256) xsplit_kernel(const float* __restrict__ x) {
    size_t idx = (size_t)blockIdx.x * 256 + threadIdx.x;   // float4 index
    if (idx < (size_t)OC * BSZ * EE) {
        S0_buf[idx] = 0.f; S1_buf[idx] = 0.f; S2_buf[idx] = 0.f;
    }
    float4 v = ((const float4*)x)[idx];
    __half hx = __float2half_rn(v.x), hy = __float2half_rn(v.y);
    __half hz = __float2half_rn(v.z), hw = __float2half_rn(v.w);
    __half lx = __float2half_rn(v.x - __half2float(hx));
    __half ly = __float2half_rn(v.y - __half2float(hy));
    __half lz = __float2half_rn(v.z - __half2float(hz));
    __half lw = __float2half_rn(v.w - __half2float(hw));
    __half2 h01 = __halves2half2(hx, hy), h23 = __halves2half2(hz, hw);
    __half2 l01 = __halves2half2(lx, ly), l23 = __halves2half2(lz, lw);
    uint2 ph, pl;
    ph.x = *(unsigned*)&h01; ph.y = *(unsigned*)&h23;
    pl.x = *(unsigned*)&l01; pl.y = *(unsigned*)&l23;
    ((uint2*)xh_buf)[idx] = ph;
    ((uint2*)xl_buf)[idx] = pl;
}

// ---------------- kernel 1: HMMA GEMM — cp.async x staging (double-buffered) ----
#define G_IPB 32
#define XP 72
#define TILE_B (64 * XP * 2)               // 9216 B
#define OFF_XH0 0
#define OFF_XH1 (1 * TILE_B)
#define OFF_XL0 (2 * TILE_B)
#define OFF_XL1 (3 * TILE_B)
#define OFF_WS  (4 * TILE_B)
#define OFF_CS  (5 * TILE_B)
#define DSM_TOTAL (6 * TILE_B)             // 55296 B

__global__ void __launch_bounds__(256, 2) gemm_kernel(const float* __restrict__ w) {
    extern __shared__ __align__(16) char dsm[];
    const uint32_t smb = smem_u32(dsm);

    const int tid  = threadIdx.x;
    const int wid  = tid >> 5;
    const int lane = tid & 31;
    const int o    = blockIdx.x;
    const int ic   = blockIdx.y;

    const int mtile = wid & 3;
    const int ehalf = wid >> 2;
    const int bbase = mtile * 16;
    const int ebase = ehalf * 32;

    const int am = (((lane >> 3) & 1) * 8) + (lane & 7);
    const int ak = (lane >> 4) * 8;
    const uint32_t aoff = (uint32_t)(((bbase + am) * XP + ak) * 2);
    const uint32_t boff = (uint32_t)(((lane & 15) * XP + ebase) * 2) + OFF_WS;

    const int ecol = 2 * (lane & 3);
    const int brow = lane >> 2;

    const int xb0 = tid >> 3,         xd0 = (tid & 7) * 8;
    const int xb1 = (tid + 256) >> 3, xd1 = (tid & 7) * 8;
    const uint32_t xs_off0 = (uint32_t)((xb0 * XP + xd0) * 2);
    const uint32_t xs_off1 = (uint32_t)((xb1 * XP + xd1) * 2);
    const size_t   xg_off0 = (size_t)xb0 * 64 + xd0;
    const size_t   xg_off1 = (size_t)xb1 * 64 + xd1;

    __half* ws = (__half*)(dsm + OFF_WS);
    __half* cs = (__half*)(dsm + OFF_CS);

    float s0[16];
    #pragma unroll
    for (int j = 0; j < 16; j++) s0[j] = 0.f;

    float4 wq[4];
    {
        const int i = ic * G_IPB;
        const __half* xh = xh_buf + (size_t)i * (BSZ * DD);
        const __half* xl = xl_buf + (size_t)i * (BSZ * DD);
        CP_ASYNC16(smb + OFF_XH0 + xs_off0, xh + xg_off0);
        CP_ASYNC16(smb + OFF_XH0 + xs_off1, xh + xg_off1);
        CP_ASYNC16(smb + OFF_XL0 + xs_off0, xl + xg_off0);
        CP_ASYNC16(smb + OFF_XL0 + xs_off1, xl + xg_off1);
        CP_COMMIT();
        const float4* wg = (const float4*)(w + (((size_t)o * ICAP + i) << 12));
        #pragma unroll
        for (int q = 0; q < 4; q++) wq[q] = wg[q * 256 + tid];
    }

    for (int ii = 0; ii < G_IPB; ii++) {
        const int i = ic * G_IPB + ii;
        const int p = ii & 1;
        const uint32_t xh_p  = (p ? OFF_XH1 : OFF_XH0);
        const uint32_t xl_p  = (p ? OFF_XL1 : OFF_XL0);
        const uint32_t xh_q  = (p ? OFF_XH0 : OFF_XH1);
        const uint32_t xl_q  = (p ? OFF_XL0 : OFF_XL1);

        #pragma unroll
        for (int q = 0; q < 4; q++) {
            int f4 = q * 256 + tid;
            int d  = f4 >> 4;
            int e4 = (f4 & 15) << 2;
            __half2 h01 = __floats2half2_rn(wq[q].x, wq[q].y);
            __half2 h23 = __floats2half2_rn(wq[q].z, wq[q].w);
            uint2 pk;
            pk.x = *(unsigned*)&h01; pk.y = *(unsigned*)&h23;
            *(uint2*)&ws[d * XP + e4] = pk;
        }

        if (ii + 1 < G_IPB) {
            const int in = i + 1;
            const __half* xh = xh_buf + (size_t)in * (BSZ * DD);
            const __half* xl = xl_buf + (size_t)in * (BSZ * DD);
            CP_ASYNC16(smb + xh_q + xs_off0, xh + xg_off0);
            CP_ASYNC16(smb + xh_q + xs_off1, xh + xg_off1);
            CP_ASYNC16(smb + xl_q + xs_off0, xl + xg_off0);
            CP_ASYNC16(smb + xl_q + xs_off1, xl + xg_off1);
        }
        CP_COMMIT();
        if (ii + 1 < G_IPB) {
            const float4* wg = (const float4*)(w + (((size_t)o * ICAP + i + 1) << 12));
            #pragma unroll
            for (int q = 0; q < 4; q++) wq[q] = wg[q * 256 + tid];
        }

        CP_WAIT1();          // x tile for i complete (own thread)
        __syncthreads();     // x + ws visible to all; u-store(i-1) done

        const uint32_t a_h = smb + xh_p + aoff;
        const uint32_t a_l = smb + xl_p + aoff;
        const uint32_t b_0 = smb + boff;

        float c[16];
        #pragma unroll
        for (int j = 0; j < 16; j++) c[j] = 0.f;

        #pragma unroll
        for (int kt = 0; kt < 4; kt++) {
            uint32_t ah0, ah1, ah2, ah3, al0, al1, al2, al3;
            LDM_X4(ah0, ah1, ah2, ah3, a_h + kt * 32);
            LDM_X4(al0, al1, al2, al3, a_l + kt * 32);
            #pragma unroll
            for (int nt = 0; nt < 4; nt++) {
                uint32_t b0, b1;
                LDM_X2_T(b0, b1, b_0 + kt * (16 * XP * 2) + nt * 16);
                MMA16816(&c[nt * 4], ah0, ah1, ah2, ah3, b0, b1);
                MMA16816(&c[nt * 4], al0, al1, al2, al3, b0, b1);
            }
        }

        #pragma unroll
        for (int nt = 0; nt < 4; nt++) {
            #pragma unroll
            for (int j = 0; j < 4; j++) s0[nt * 4 + j] += c[nt * 4 + j];
            int e0 = ebase + nt * 8 + ecol;
            __half2 p0 = __floats2half2_rn(c[nt * 4 + 0], c[nt * 4 + 1]);
            __half2 p1 = __floats2half2_rn(c[nt * 4 + 2], c[nt * 4 + 3]);
            *(__half2*)&cs[(bbase + brow) * XP + e0]     = p0;
            *(__half2*)&cs[(bbase + brow + 8) * XP + e0] = p1;
        }
        __syncthreads();

        {
            uint4* ubase = (uint4*)(u_buf + ((size_t)i * OC + o) * (BSZ * EE));
            int t0 = tid, t1 = tid + 256;
            ubase[t0] = *(uint4*)&cs[(t0 >> 3) * XP + (t0 & 7) * 8];
            ubase[t1] = *(uint4*)&cs[(t1 >> 3) * XP + (t1 & 7) * 8];
        }
    }

    #pragma unroll
    for (int nt = 0; nt < 4; nt++) {
        int e0 = ebase + nt * 8 + ecol;
        int b0 = bbase + brow;
        atomicAdd(&S0_buf[(o * BSZ + b0) * EE + e0],     s0[nt * 4 + 0]);
        atomicAdd(&S0_buf[(o * BSZ + b0) * EE + e0 + 1], s0[nt * 4 + 1]);
        atomicAdd(&S0_buf[(o * BSZ + b0 + 8) * EE + e0],     s0[nt * 4 + 2]);
        atomicAdd(&S0_buf[(o * BSZ + b0 + 8) * EE + e0 + 1], s0[nt * 4 + 3]);
    }
}

// ---------------- routing scan (R11 version — best measured) ----------------
#define RIPB 32
__global__ void __launch_bounds__(128, 2) route_iter_kernel(int phase) {
    const float* vprev = (phase == 1) ? v0_buf : v1_buf;
    float* Sout        = (phase == 1) ? S1_buf : S2_buf;

    __shared__ float esum[2][2][2][2];   // [buf][ig][ab][w]
    __shared__ float Sred[4][16][66];    // [warp][o-row][e]

    const int b    = blockIdx.x;
    const int i0   = blockIdx.y * RIPB;
    const int tid  = threadIdx.x;
    const int warp = tid >> 5;
    const int L    = tid & 31;
    const int w    = warp & 1;
    const int ig   = warp >> 1;
    const int g    = L >> 3;
    const int p    = L & 7;

    unsigned long long vs[4][4];
    #pragma unroll
    for (int k = 0; k < 4; k++) {
        int o = w * 16 + k * 4 + g;
        const float4* vg = (const float4*)(vprev + (o * BSZ + b) * EE + p * 8);
        float4 v0 = vg[0], v1 = vg[1];
        F2U t0, t1, t2, t3;
        t0.f = make_float2(v0.x, v0.y); t1.f = make_float2(v0.z, v0.w);
        t2.f = make_float2(v1.x, v1.y); t3.f = make_float2(v1.z, v1.w);
        vs[k][0] = t0.u; vs[k][1] = t1.u; vs[k][2] = t2.u; vs[k][3] = t3.u;
    }

    unsigned long long S[4][4];
    #pragma unroll
    for (int k = 0; k < 4; k++)
        #pragma unroll
        for (int j = 0; j < 4; j++) S[k][j] = 0ull;

    const uint4* ub4 = (const uint4*)u_buf;
    const uint4* bb4 = (const uint4*)beta_buf;
    const int lconst = g * 512 + p;

    uint4 qA[2][4], qB[2][4];
    float4 bpA[2], bpB[2];

    {
        const int iA = i0 + ig, iB = iA + 2;
        const size_t baseA = (((size_t)iA * OC + w * 16) * BSZ + b) * 8;
        const size_t baseB = (((size_t)iB * OC + w * 16) * BSZ + b) * 8;
        #pragma unroll
        for (int k = 0; k < 4; k++) {
            qA[0][k] = __ldg(ub4 + baseA + k * 2048 + lconst);
            qB[0][k] = __ldg(ub4 + baseB + k * 2048 + lconst);
        }
        if (phase == 2) {
            bpA[0] = *(const float4*)(bb4 + ((((size_t)iA * BSZ + b) * 2 + w) * 4 + g));
            bpB[0] = *(const float4*)(bb4 + ((((size_t)iB * BSZ + b) * 2 + w) * 4 + g));
        }
    }

    #pragma unroll
    for (int tb = 0; tb < 8; tb++) {
        const int cur = tb & 1, nxt = cur ^ 1;
        const int iA = i0 + tb * 4 + ig;
        const int iB = iA + 2;

        if (tb < 7) {
            const int jA = iA + 4, jB = iB + 4;
            const size_t baseA = (((size_t)jA * OC + w * 16) * BSZ + b) * 8;
            const size_t baseB = (((size_t)jB * OC + w * 16) * BSZ + b) * 8;
            #pragma unroll
            for (int k = 0; k < 4; k++) {
                qA[nxt][k] = __ldg(ub4 + baseA + k * 2048 + lconst);
                qB[nxt][k] = __ldg(ub4 + baseB + k * 2048 + lconst);
            }
            if (phase == 2) {
                bpA[nxt] = *(const float4*)(bb4 + ((((size_t)jA * BSZ + b) * 2 + w) * 4 + g));
                bpB[nxt] = *(const float4*)(bb4 + ((((size_t)jB * BSZ + b) * 2 + w) * 4 + g));
            }
        }

        float betA[4], betB[4];
        #pragma unroll
        for (int k = 0; k < 4; k++) {
            unsigned long long dA = 0ull, dB = 0ull;
            const __half2* hA = (const __half2*)&qA[cur][k];
            const __half2* hB = (const __half2*)&qB[cur][k];
            #pragma unroll
            for (int j = 0; j < 4; j++) {
                F2U a; a.f = __half22float2(hA[j]);
                FMA2(dA, a.u, vs[k][j], dA);
                F2U c; c.f = __half22float2(hB[j]);
                FMA2(dB, c.u, vs[k][j], dB);
            }
            F2U rA; rA.u = dA; float fA = rA.f.x + rA.f.y;
            F2U rB; rB.u = dB; float fB = rB.f.x + rB.f.y;
            #pragma unroll
            for (int s = 1; s < 8; s <<= 1) {
                fA += __shfl_xor_sync(0xffffffffu, fA, s);
                fB += __shfl_xor_sync(0xffffffffu, fB, s);
            }
            betA[k] = fA; betB[k] = fB;
        }

        if (phase == 2) {
            betA[0] += bpA[cur].x; betA[1] += bpA[cur].y;
            betA[2] += bpA[cur].z; betA[3] += bpA[cur].w;
            betB[0] += bpB[cur].x; betB[1] += bpB[cur].y;
            betB[2] += bpB[cur].z; betB[3] += bpB[cur].w;
        } else if (p == 0) {
            *(uint4*)(bb4 + ((((size_t)iA * BSZ + b) * 2 + w) * 4 + g)) = *(uint4*)betA;
            *(uint4*)(bb4 + ((((size_t)iB * BSZ + b) * 2 + w) * 4 + g)) = *(uint4*)betB;
        }

        float eA[4], eB[4], sA = 0.f, sB = 0.f;
        #pragma unroll
        for (int k = 0; k < 4; k++) {
            eA[k] = __expf(betA[k]); sA += eA[k];
            eB[k] = __expf(betB[k]); sB += eB[k];
        }
        sA += __shfl_xor_sync(0xffffffffu, sA, 8);
        sA += __shfl_xor_sync(0xffffffffu, sA, 16);
        sB += __shfl_xor_sync(0xffffffffu, sB, 8);
        sB += __shfl_xor_sync(0xffffffffu, sB, 16);

        if (L == 0) { esum[cur][ig][0][w] = sA; esum[cur][ig][1][w] = sB; }
        asm volatile("bar.sync %0, %1;" :: "r"(1 + ig), "r"(64) : "memory");
        float rA = __fdividef(1.f, sA + esum[cur][ig][0][w ^ 1]);
        float rB = __fdividef(1.f, sB + esum[cur][ig][1][w ^ 1]);

        #pragma unroll
        for (int k = 0; k < 4; k++) {
            F2U cdA; float cA = eA[k] * rA; cdA.f = make_float2(cA, cA);
            F2U cdB; float cB = eB[k] * rB; cdB.f = make_float2(cB, cB);
            const __half2* hA = (const __half2*)&qA[cur][k];
            const __half2* hB = (const __half2*)&qB[cur][k];
            #pragma unroll
            for (int j = 0; j < 4; j++) {
                F2U a; a.f = __half22float2(hA[j]);
                FMA2(S[k][j], cdA.u, a.u, S[k][j]);
                F2U c; c.f = __half22float2(hB[j]);
                FMA2(S[k][j], cdB.u, c.u, S[k][j]);
            }
        }
    }

    #pragma unroll
    for (int k = 0; k < 4; k++)
        #pragma unroll
        for (int j = 0; j < 4; j++) {
            F2U s; s.u = S[k][j];
            Sred[warp][k * 4 + g][p * 8 + 2 * j]     = s.f.x;
            Sred[warp][k * 4 + g][p * 8 + 2 * j + 1] = s.f.y;
        }
    __syncthreads();

    for (int t = tid; t < 2048; t += 128) {
        int half = t >> 10;
        int row  = (t >> 6) & 15;
        int e    = t & 63;
        float v = Sred[half][row][e] + Sred[2 + half][row][e];
        int o = half * 16 + row;
        atomicAdd(&Sout[(o * BSZ + b) * EE + e], v);
    }
}

// ---------------- squash: v = s * sqrt(|s|^2)/(1+|s|^2) ----------------
__global__ void squash_kernel(int which, float* __restrict__ out) {
    int row  = blockIdx.x * 8 + (threadIdx.x >> 5);
    int lane = threadIdx.x & 31;
    const float* Sin = (which == 0) ? S0_buf : (which == 1 ? S1_buf : S2_buf);
    float* vout      = (which == 0) ? v0_buf : (which == 1 ? v1_buf : out);
    float factor     = (which == 0) ? (1.0f / 32.0f) : 1.0f;   // softmax(0) = 1/32

    float a = Sin[row * 64 + lane] * factor;
    float c = Sin[row * 64 + 32 + lane] * factor;
    float sq = a * a + c * c;
    #pragma unroll
    for (int s = 16; s; s >>= 1) sq += __shfl_xor_sync(0xffffffffu, sq, s);
    float scale = sqrtf(sq) / (1.0f + sq);
    vout[row * 64 + lane]      = a * scale;
    vout[row * 64 + 32 + lane] = c * scale;
}

// ---------------- launch ----------------
extern "C" void kernel_launch(void* const* d_in, const int* in_sizes, int n_in,
                              void* d_out, int out_size) {
    const float* x = (const float*)d_in[0];       // [1024, 64, 64]
    const float* w = (const float*)d_in[1];       // [32, 1024, 64, 64]
    if (n_in >= 2 && in_sizes[0] > in_sizes[1]) { const float* t = x; x = w; w = t; }
    float* out = (float*)d_out;                   // [32, 64, 64]

    cudaFuncSetAttribute(gemm_kernel, cudaFuncAttributeMaxDynamicSharedMemorySize,
                         DSM_TOTAL);

    xsplit_kernel<<<4096, 256>>>(x);              // also zeroes S0/S1/S2

    dim3 gG(OC, ICAP / G_IPB);                    // (32 o, 32 i-chunks)
    gemm_kernel<<<gG, 256, DSM_TOTAL>>>(w);

    squash_kernel<<<256, 256>>>(0, nullptr);

    dim3 gR(BSZ, ICAP / RIPB);                    // (64, 32)
    route_iter_kernel<<<gR, 128>>>(1);
    squash_kernel<<<256, 256>>>(1, nullptr);
    route_iter_kernel<<<gR, 128>>>(2);
    squash_kernel<<<256, 256>>>(2, out);
}